// round 8
// baseline (speedup 1.0000x reference)
#include <cuda_runtime.h>

#define NB 8
#define PP 2304
#define QTOT (NB*PP)       // 18432
#define CIN 64
#define OUTC 384
#define NSTRIDE (OUTC*PP)
#define SLICE (64*PP)
#define NS 9               // split-K factor for visual attention
#define COLW 56            // (qkv0 only) smem row width
#define QAP 52             // mega qA pitch (floats)
#define QBP 52             // mega qB pitch
#define XP  68             // mega xsm pitch
#define CVP 36             // mega conv-partial pitch

// Scratch (allocation-free rule: __device__ globals)
__device__ float g_q[NB*8*PP];
__device__ float g_k[NB*8*PP];
__device__ float g_v[NB*32*PP];
__device__ float g_pl[NS*QTOT];
__device__ float g_pv[NS*32*QTOT];
__device__ float g_x[QTOT*64];     // [p][n][c] mega-kernel input

typedef unsigned long long u64;

__device__ __forceinline__ u64 fma2(u64 a,u64 b,u64 c){u64 d;asm("fma.rn.f32x2 %0,%1,%2,%3;":"=l"(d):"l"(a),"l"(b),"l"(c));return d;}
__device__ __forceinline__ u64 add2(u64 a,u64 b){u64 d;asm("add.rn.f32x2 %0,%1,%2;":"=l"(d):"l"(a),"l"(b));return d;}
__device__ __forceinline__ u64 pack2(float lo,float hi){u64 d;asm("mov.b64 %0,{%1,%2};":"=l"(d):"f"(lo),"f"(hi));return d;}
__device__ __forceinline__ void unpack2(u64 v,float&lo,float&hi){asm("mov.b64 {%0,%1},%2;":"=f"(lo),"=f"(hi):"l"(v));}

__device__ __forceinline__ float dot4(float4 a, float4 b){
    return a.x*b.x + a.y*b.y + a.z*b.z + a.w*b.w;
}

// ---------------------------------------------------------------------------
// Stage-0 QKV, 4-way split (unchanged from passing versions).
// ---------------------------------------------------------------------------
__global__ __launch_bounds__(128) void qkv0_kernel(
    const float* __restrict__ src,
    const float* __restrict__ qw, const float* __restrict__ qb,
    const float* __restrict__ kw, const float* __restrict__ kb,
    const float* __restrict__ vw, const float* __restrict__ vb)
{
    __shared__ alignas(16) float swt[64*52];
    __shared__ alignas(16) float sbs[48];
    __shared__ alignas(16) float xsm[64*COLW];

    const int tid = threadIdx.x;
    const int wq = tid >> 5, l = tid & 31;
    const int pos = l & 3, n = l >> 2;
    const int col = 8 + pos*12 + n;
    const int pg = blockIdx.x*4;

    for (int i = tid; i < 48*64; i += 128) {
        int o = i >> 6, c = i & 63;
        float wv = (o<8) ? qw[o*64+c] : (o<16) ? kw[(o-8)*64+c] : vw[(o-16)*64+c];
        swt[c*52 + o] = wv;
    }
    if (tid < 48) sbs[tid] = (tid<8)? qb[tid] : (tid<16? kb[tid-8] : vb[tid-16]);
    for (int i = tid; i < 64*32; i += 128) {
        int c = i >> 5, ce = i & 31;
        int pp_ = ce & 3, nn = ce >> 2;
        xsm[c*COLW + (8 + pp_*12 + nn)] = src[(long)nn*CIN*PP + (long)c*PP + pg + pp_];
    }
    __syncthreads();

    u64 acc[6];
    {
        const u64* bp = (const u64*)sbs;
        #pragma unroll
        for (int t=0;t<6;t++) acc[t] = bp[wq*6 + t];
    }
    #pragma unroll 8
    for (int c=0;c<64;c++) {
        float xv = xsm[c*COLW + col];
        u64 x2 = pack2(xv,xv);
        const ulonglong2* wr = (const ulonglong2*)(swt + c*52 + wq*12);
        ulonglong2 w0 = wr[0], w1 = wr[1], w2 = wr[2];
        acc[0]=fma2(x2,w0.x,acc[0]); acc[1]=fma2(x2,w0.y,acc[1]);
        acc[2]=fma2(x2,w1.x,acc[2]); acc[3]=fma2(x2,w1.y,acc[3]);
        acc[4]=fma2(x2,w2.x,acc[4]); acc[5]=fma2(x2,w2.y,acc[5]);
    }
    float o12[12];
    #pragma unroll
    for (int t=0;t<6;t++) unpack2(acc[t], o12[2*t], o12[2*t+1]);
    const int p = pg + pos;
    #pragma unroll
    for (int t=0;t<12;t++) {
        int o = wq*12 + t;
        if (o < 8)       g_q[(n*8  + o     )*PP + p] = o12[t];
        else if (o < 16) g_k[(n*8  + (o-8) )*PP + p] = o12[t];
        else             g_v[(n*32 + (o-16))*PP + p] = fmaxf(o12[t], 0.f);
    }
}

// ---------------------------------------------------------------------------
// Visual attention, split-K — REVERTED to the round-3/6 layout ([t][j] smem).
// ---------------------------------------------------------------------------
__global__ __launch_bounds__(128) void vis_attn_split(void)
{
    __shared__ alignas(16) u64 ksu[4*128];    // [c2][j]
    __shared__ alignas(16) u64 vsu[16*128];   // [c2][j]
    const int tid = threadIdx.x;
    const int tile = blockIdx.x / NS, split = blockIdx.x % NS;
    const int n = tile / 6, tw = tile % 6;
    const int qp = tw*384 + tid;
    const float* qb_ = g_q + n*8*PP;
    const float* kb_ = g_k + n*8*PP;
    const float* vb_ = g_v + n*32*PP;

    u64 qr[3][4];
    #pragma unroll
    for (int i=0;i<3;i++)
        #pragma unroll
        for (int r=0;r<4;r++)
            qr[i][r] = pack2(qb_[(2*r)*PP + qp + i*128], qb_[(2*r+1)*PP + qp + i*128]);

    float l[3] = {0.f, 0.f, 0.f};
    u64 vacc[3][16];
    #pragma unroll
    for (int i=0;i<3;i++)
        #pragma unroll
        for (int t=0;t<16;t++) vacc[i][t] = 0ULL;

    const u64 z = 0ULL;
    for (int ch = split*2; ch < split*2 + 2; ch++) {
        __syncthreads();
        const int base = ch*128 + tid;
        #pragma unroll
        for (int r=0;r<4;r++)  ksu[r*128+tid] = pack2(kb_[(2*r)*PP+base], kb_[(2*r+1)*PP+base]);
        #pragma unroll
        for (int t=0;t<16;t++) vsu[t*128+tid] = pack2(vb_[(2*t)*PP+base], vb_[(2*t+1)*PP+base]);
        __syncthreads();
        #pragma unroll 2
        for (int j=0;j<128;j++) {
            u64 k0 = ksu[j], k1 = ksu[128+j], k2 = ksu[256+j], k3 = ksu[384+j];
            float pr[3];
            #pragma unroll
            for (int i=0;i<3;i++) {
                u64 d = add2(fma2(qr[i][0],k0,fma2(qr[i][1],k1,z)),
                             fma2(qr[i][2],k2,fma2(qr[i][3],k3,z)));
                float lo,hi; unpack2(d,lo,hi);
                pr[i] = __expf(lo + hi);
                l[i] += pr[i];
            }
            u64 p0 = pack2(pr[0],pr[0]), p1 = pack2(pr[1],pr[1]), p2 = pack2(pr[2],pr[2]);
            #pragma unroll
            for (int t=0;t<16;t++) {
                u64 vr = vsu[t*128+j];
                vacc[0][t] = fma2(p0, vr, vacc[0][t]);
                vacc[1][t] = fma2(p1, vr, vacc[1][t]);
                vacc[2][t] = fma2(p2, vr, vacc[2][t]);
            }
        }
    }
    #pragma unroll
    for (int i=0;i<3;i++) {
        int q = n*PP + qp + i*128;
        g_pl[split*QTOT + q] = l[i];
        #pragma unroll
        for (int t=0;t<16;t++) {
            float lo,hi; unpack2(vacc[i][t], lo, hi);
            g_pv[(split*32 + 2*t  )*QTOT + q] = lo;
            g_pv[(split*32 + 2*t+1)*QTOT + q] = hi;
        }
    }
}

// ---------------------------------------------------------------------------
// Combine split-K partials (unchanged from passing versions).
// ---------------------------------------------------------------------------
__global__ __launch_bounds__(128) void combine_kernel(
    const float* __restrict__ cw, const float* __restrict__ cb,
    float* __restrict__ out)
{
    __shared__ alignas(16) u64 cwt[32*16];
    __shared__ alignas(16) float cbs[32];
    const int tid = threadIdx.x;
    for (int i = tid; i < 32*16; i += 128) {
        int c = i/16, t = i%16;
        cwt[i] = pack2(cw[(2*t)*32+c], cw[(2*t+1)*32+c]);
    }
    if (tid < 32) cbs[tid] = cb[tid];
    __syncthreads();

    const int gid = blockIdx.x*128 + tid;
    const int n = gid/PP, p = gid%PP;

    float l = 0.f;
    #pragma unroll
    for (int sp=0; sp<NS; sp++) l += g_pl[sp*QTOT + gid];
    float va[32];
    #pragma unroll
    for (int c=0;c<32;c++) va[c] = 0.f;
    for (int sp=0; sp<NS; sp++) {
        #pragma unroll
        for (int c=0;c<32;c++) va[c] += g_pv[(sp*32+c)*QTOT + gid];
    }
    float inv = 1.f / l;
    #pragma unroll
    for (int c=0;c<32;c++) va[c] *= inv;

    u64 acc[16];
    #pragma unroll
    for (int t=0;t<16;t++) acc[t] = pack2(cbs[2*t], cbs[2*t+1]);
    #pragma unroll
    for (int c=0;c<32;c++) {
        u64 x2 = pack2(va[c], va[c]);
        const ulonglong2* w2 = (const ulonglong2*)(cwt + c*16);
        #pragma unroll
        for (int t=0;t<8;t++){ ulonglong2 w = w2[t];
            acc[2*t] = fma2(x2,w.x,acc[2*t]); acc[2*t+1] = fma2(x2,w.y,acc[2*t+1]); }
    }
    float buf[64];
    #pragma unroll
    for (int t=0;t<16;t++) unpack2(acc[t], buf[2*t], buf[2*t+1]);
    #pragma unroll
    for (int c=0;c<32;c++) buf[32+c] = g_v[(n*32+c)*PP+p];

    float* ob = out + (long)n*NSTRIDE + p;
    #pragma unroll
    for (int o=0;o<32;o++) ob[o*PP] = buf[o];
    #pragma unroll
    for (int c=0;c<32;c++) ob[(32+c)*PP] = buf[32+c];

    float4* xp = (float4*)(g_x + ((long)p*8 + n)*64);
    #pragma unroll
    for (int t=0;t<16;t++) xp[t] = make_float4(buf[4*t],buf[4*t+1],buf[4*t+2],buf[4*t+3]);
}

// ---------------------------------------------------------------------------
// MEGA temporal v4: 256 threads, 32 cells, k-split across warp pairs.
// warp wid: og = wid&3 (output group), kh = wid>>2 (k half).
// Thread (wid,lane): cell = lane (pos = lane>>3, n = lane&7).
// qkv: outputs [12og,12og+12), k in [32kh,32kh+32) -> partials qA/qB;
// merge pass combines + applies ReLU (post-merge — ReLU is nonlinear).
// softmax: redundant per thread. conv: outputs [8og,8og+8), v-ch [16kh,16kh+16).
// precede(): guard rows keep neighbor reads in-bounds; selects zero the
// padded-frame logits and weights (exactly reference zero-frame semantics).
// ---------------------------------------------------------------------------
__global__ __launch_bounds__(256) void mega_temporal(
    const float* __restrict__ tq_w, const float* __restrict__ tq_b,
    const float* __restrict__ tk_w, const float* __restrict__ tk_b,
    const float* __restrict__ tv_w, const float* __restrict__ tv_b,
    const float* __restrict__ tc_w, const float* __restrict__ tc_b,
    float* __restrict__ out)
{
    __shared__ alignas(16) float swt[64*48];    // qkv weights [c][o]
    __shared__ alignas(16) float cwt[32*CVP];   // conv weights [c][o]
    __shared__ alignas(16) float sbs[48];
    __shared__ alignas(16) float cbs[32];
    __shared__ alignas(16) float xsm[32*XP];    // head input [cell][c]
    __shared__ alignas(16) float qA[34*QAP];    // kh=0 partials; rows 0,1 guards
    __shared__ alignas(16) float qB[32*QBP];    // kh=1 partials
    __shared__ alignas(16) float cvA[32*CVP];   // conv partials kh=0
    __shared__ alignas(16) float cvB[32*CVP];   // conv partials kh=1

    const int tid  = threadIdx.x;
    const int wid  = tid >> 5, lane = tid & 31;
    const int og   = wid & 3, kh = wid >> 2;
    const int cell = lane, n = lane & 7;
    const int rowA = 2 + cell;
    const int pg   = blockIdx.x*4;
    const int cg   = tid >> 3, gg = tid & 7;   // final-phase mapping

    // init: zero guard rows; load head-0 input (2 float4 per thread)
    if (tid < 2*QAP) qA[tid] = 0.f;
    {
        int posI = cg >> 3, nI = cg & 7;
        const float* gx = g_x + ((long)(pg+posI)*8 + nI)*64;
        *(float4*)(xsm + cg*XP + 4*gg)      = *(const float4*)(gx + 4*gg);
        *(float4*)(xsm + cg*XP + 32 + 4*gg) = *(const float4*)(gx + 32 + 4*gg);
    }

    for (int h=0; h<5; h++) {
        __syncthreads();   // A: xsm complete; prior-head smem reads done

        for (int i = tid; i < 48*64; i += 256) {
            int o = i >> 6, c = i & 63;
            float wv = (o<8)  ? tq_w[h*512  + o*64 + c]
                     : (o<16) ? tk_w[h*512  + (o-8)*64 + c]
                              : tv_w[h*2048 + (o-16)*64 + c];
            swt[c*48 + o] = wv;
        }
        for (int i = tid; i < 32*32; i += 256) {
            int o = i >> 5, c = i & 31;
            cwt[c*CVP + o] = tc_w[h*1024 + o*32 + c];
        }
        if (tid < 48) sbs[tid] = (tid<8)? tq_b[h*8+tid] : (tid<16? tk_b[h*8+tid-8] : tv_b[h*32+tid-16]);
        if (tid < 32) cbs[tid] = tc_b[h*32+tid];
        __syncthreads();   // B: weights ready

        // ---- qkv partial GEMM
        u64 acc[6];
        if (kh == 0) {
            const u64* bp = (const u64*)sbs;
            #pragma unroll
            for (int t=0;t<6;t++) acc[t] = bp[og*6 + t];
        } else {
            #pragma unroll
            for (int t=0;t<6;t++) acc[t] = 0ULL;
        }
        {
            const float* xr = xsm + cell*XP + 32*kh;
            #pragma unroll
            for (int c4=0; c4<32; c4+=4) {
                float4 xv = *(const float4*)(xr + c4);
                float xs[4] = {xv.x, xv.y, xv.z, xv.w};
                #pragma unroll
                for (int j=0;j<4;j++) {
                    u64 x2 = pack2(xs[j], xs[j]);
                    const ulonglong2* wr = (const ulonglong2*)(swt + (32*kh+c4+j)*48 + og*12);
                    ulonglong2 w0 = wr[0], w1 = wr[1], w2 = wr[2];
                    acc[0]=fma2(x2,w0.x,acc[0]); acc[1]=fma2(x2,w0.y,acc[1]);
                    acc[2]=fma2(x2,w1.x,acc[2]); acc[3]=fma2(x2,w1.y,acc[3]);
                    acc[4]=fma2(x2,w2.x,acc[4]); acc[5]=fma2(x2,w2.y,acc[5]);
                }
            }
            float o12[12];
            #pragma unroll
            for (int t=0;t<6;t++) unpack2(acc[t], o12[2*t], o12[2*t+1]);
            float* w = kh ? (qB + cell*QBP + og*12) : (qA + rowA*QAP + og*12);
            *(float4*)(w  ) = make_float4(o12[0],o12[1],o12[2],o12[3]);
            *(float4*)(w+4) = make_float4(o12[4],o12[5],o12[6],o12[7]);
            *(float4*)(w+8) = make_float4(o12[8],o12[9],o12[10],o12[11]);
        }
        __syncthreads();   // C: partials ready

        // ---- merge k-halves (+ ReLU on v outputs)
        for (int i = tid; i < 384; i += 256) {
            int mc = i / 12, mg = i % 12;
            float4 a = *(const float4*)(qA + (2+mc)*QAP + 4*mg);
            float4 b = *(const float4*)(qB + mc*QBP + 4*mg);
            a.x += b.x; a.y += b.y; a.z += b.z; a.w += b.w;
            if (mg >= 4) {   // outputs 16..47 = v -> ReLU
                a.x = fmaxf(a.x,0.f); a.y = fmaxf(a.y,0.f);
                a.z = fmaxf(a.z,0.f); a.w = fmaxf(a.w,0.f);
            }
            *(float4*)(qA + (2+mc)*QAP + 4*mg) = a;
        }
        __syncthreads();   // D: merged qkv ready

        // ---- softmax (redundant per thread; own cell)
        float a0, a1, a2;
        {
            const float* rp = qA + rowA*QAP;
            float4 q0=*(const float4*)(rp),   q1=*(const float4*)(rp+4);
            float4 k0a=*(const float4*)(rp+8),        k0b=*(const float4*)(rp+12);
            float4 k1a=*(const float4*)(rp+8-QAP),    k1b=*(const float4*)(rp+12-QAP);
            float4 k2a=*(const float4*)(rp+8-2*QAP),  k2b=*(const float4*)(rp+12-2*QAP);
            float l2 = dot4(q0,k0a)+dot4(q1,k0b);
            float l1 = (n>=1) ? dot4(q0,k1a)+dot4(q1,k1b) : 0.f;
            float l0 = (n>=2) ? dot4(q0,k2a)+dot4(q1,k2b) : 0.f;
            float m  = fmaxf(l0, fmaxf(l1, l2));
            float e0=__expf(l0-m), e1=__expf(l1-m), e2=__expf(l2-m);
            float inv = 1.f/(e0+e1+e2);
            a2 = e2*inv;
            a1 = (n>=1) ? e1*inv : 0.f;
            a0 = (n>=2) ? e0*inv : 0.f;
        }

        // ---- conv partial GEMM (attention combine fused in)
        u64 ca[4];
        if (kh == 0) {
            const u64* bp = (const u64*)cbs;
            #pragma unroll
            for (int t=0;t<4;t++) ca[t] = bp[og*4 + t];
        } else {
            #pragma unroll
            for (int t=0;t<4;t++) ca[t] = 0ULL;
        }
        {
            const float* vr = qA + rowA*QAP + 16 + 16*kh;
            #pragma unroll
            for (int c4=0; c4<16; c4+=4) {
                float4 v0=*(const float4*)(vr+c4);
                float4 v1=*(const float4*)(vr+c4-QAP);
                float4 v2=*(const float4*)(vr+c4-2*QAP);
                float av[4];
                av[0]=a2*v0.x+a1*v1.x+a0*v2.x; av[1]=a2*v0.y+a1*v1.y+a0*v2.y;
                av[2]=a2*v0.z+a1*v1.z+a0*v2.z; av[3]=a2*v0.w+a1*v1.w+a0*v2.w;
                #pragma unroll
                for (int j=0;j<4;j++) {
                    u64 x2 = pack2(av[j], av[j]);
                    const ulonglong2* wr = (const ulonglong2*)(cwt + (16*kh+c4+j)*CVP + og*8);
                    ulonglong2 w0 = wr[0], w1 = wr[1];
                    ca[0]=fma2(x2,w0.x,ca[0]); ca[1]=fma2(x2,w0.y,ca[1]);
                    ca[2]=fma2(x2,w1.x,ca[2]); ca[3]=fma2(x2,w1.y,ca[3]);
                }
            }
            float oc8[8];
            #pragma unroll
            for (int t=0;t<4;t++) unpack2(ca[t], oc8[2*t], oc8[2*t+1]);
            float* cw_ = (kh ? cvB : cvA) + cell*CVP + og*8;
            *(float4*)(cw_  ) = make_float4(oc8[0],oc8[1],oc8[2],oc8[3]);
            *(float4*)(cw_+4) = make_float4(oc8[4],oc8[5],oc8[6],oc8[7]);
        }
        __syncthreads();   // E: conv partials ready

        // ---- final: merge conv partials, store out, build next xsm
        {
            int posF = cg >> 3, nF = cg & 7;
            float4 a = *(const float4*)(cvA + cg*CVP + 4*gg);
            float4 b = *(const float4*)(cvB + cg*CVP + 4*gg);
            float oc[4] = {a.x+b.x, a.y+b.y, a.z+b.z, a.w+b.w};
            float4 v4 = *(const float4*)(qA + (2+cg)*QAP + 16 + 4*gg);

            float* ob = out + (long)nF*NSTRIDE + (long)(h+1)*SLICE + pg + posF;
            ob[(4*gg+0)*PP] = oc[0]; ob[(4*gg+1)*PP] = oc[1];
            ob[(4*gg+2)*PP] = oc[2]; ob[(4*gg+3)*PP] = oc[3];
            ob[(32+4*gg+0)*PP] = v4.x; ob[(32+4*gg+1)*PP] = v4.y;
            ob[(32+4*gg+2)*PP] = v4.z; ob[(32+4*gg+3)*PP] = v4.w;

            *(float4*)(xsm + cg*XP + 4*gg)      = make_float4(oc[0],oc[1],oc[2],oc[3]);
            *(float4*)(xsm + cg*XP + 32 + 4*gg) = v4;
        }
    }
}

// ---------------------------------------------------------------------------
extern "C" void kernel_launch(void* const* d_in, const int* in_sizes, int n_in,
                              void* d_out, int out_size)
{
    const float* x    = (const float*)d_in[0];
    const float* vq_w = (const float*)d_in[1];
    const float* vq_b = (const float*)d_in[2];
    const float* vk_w = (const float*)d_in[3];
    const float* vk_b = (const float*)d_in[4];
    const float* vv_w = (const float*)d_in[5];
    const float* vv_b = (const float*)d_in[6];
    const float* vc_w = (const float*)d_in[7];
    const float* vc_b = (const float*)d_in[8];
    const float* tq_w = (const float*)d_in[9];
    const float* tq_b = (const float*)d_in[10];
    const float* tk_w = (const float*)d_in[11];
    const float* tk_b = (const float*)d_in[12];
    const float* tv_w = (const float*)d_in[13];
    const float* tv_b = (const float*)d_in[14];
    const float* tc_w = (const float*)d_in[15];
    const float* tc_b = (const float*)d_in[16];
    float* out = (float*)d_out;

    qkv0_kernel<<<576,128>>>(x, vq_w, vq_b, vk_w, vk_b, vv_w, vv_b);
    vis_attn_split<<<48*NS,128>>>();
    combine_kernel<<<144,128>>>(vc_w, vc_b, out);
    mega_temporal<<<576,256>>>(tq_w, tq_b, tk_w, tk_b, tv_w, tv_b, tc_w, tc_b, out);
}

// round 10
// speedup vs baseline: 1.4304x; 1.4304x over previous
#include <cuda_runtime.h>

#define NB 8
#define PP 2304
#define QTOT (NB*PP)       // 18432
#define CIN 64
#define OUTC 384
#define NSTRIDE (OUTC*PP)
#define SLICE (64*PP)
#define NS 9               // split-K factor for visual attention
#define COLW 56            // (qkv0 only) smem row width

// Scratch (allocation-free rule: __device__ globals)
__device__ float g_q[NB*8*PP];
__device__ float g_k[NB*8*PP];
__device__ float g_v[NB*32*PP];
__device__ float g_pl[NS*QTOT];
__device__ float g_pv[NS*32*QTOT];
__device__ float g_x[QTOT*64];     // [p][n][c] mega-kernel input
__device__ float g_wt[5*4096];     // per head: [64][48] qkv-T (3072) + [32][32] conv-T (1024)

typedef unsigned long long u64;

__device__ __forceinline__ u64 fma2(u64 a,u64 b,u64 c){u64 d;asm("fma.rn.f32x2 %0,%1,%2,%3;":"=l"(d):"l"(a),"l"(b),"l"(c));return d;}
__device__ __forceinline__ u64 add2(u64 a,u64 b){u64 d;asm("add.rn.f32x2 %0,%1,%2;":"=l"(d):"l"(a),"l"(b));return d;}
__device__ __forceinline__ u64 pack2(float lo,float hi){u64 d;asm("mov.b64 %0,{%1,%2};":"=l"(d):"f"(lo),"f"(hi));return d;}
__device__ __forceinline__ void unpack2(u64 v,float&lo,float&hi){asm("mov.b64 {%0,%1},%2;":"=f"(lo),"=f"(hi):"l"(v));}

__device__ __forceinline__ float dot4(float4 a, float4 b){
    return a.x*b.x + a.y*b.y + a.z*b.z + a.w*b.w;
}

// ---------------------------------------------------------------------------
// One-shot weight transpose: [o][c] (gmem) -> [c][o] flat per head in g_wt.
// Scattered LDG, linear STG; runs once per launch, ~2 us.
// ---------------------------------------------------------------------------
__global__ __launch_bounds__(256) void transpose_w(
    const float* __restrict__ tq_w, const float* __restrict__ tk_w,
    const float* __restrict__ tv_w, const float* __restrict__ tc_w)
{
    int i = blockIdx.x*256 + threadIdx.x;
    if (i >= 5*4096) return;
    int h = i >> 12, r = i & 4095;
    float v;
    if (r < 3072) {
        int c = r / 48, o = r % 48;
        v = (o<8)  ? tq_w[h*512  + o*64 + c]
          : (o<16) ? tk_w[h*512  + (o-8)*64 + c]
                   : tv_w[h*2048 + (o-16)*64 + c];
    } else {
        int rr = r - 3072;
        int c = rr >> 5, o = rr & 31;
        v = tc_w[h*1024 + o*32 + c];
    }
    g_wt[i] = v;
}

// ---------------------------------------------------------------------------
// Stage-0 QKV, 4-way split (unchanged from passing versions).
// ---------------------------------------------------------------------------
__global__ __launch_bounds__(128) void qkv0_kernel(
    const float* __restrict__ src,
    const float* __restrict__ qw, const float* __restrict__ qb,
    const float* __restrict__ kw, const float* __restrict__ kb,
    const float* __restrict__ vw, const float* __restrict__ vb)
{
    __shared__ alignas(16) float swt[64*52];
    __shared__ alignas(16) float sbs[48];
    __shared__ alignas(16) float xsm[64*COLW];

    const int tid = threadIdx.x;
    const int wq = tid >> 5, l = tid & 31;
    const int pos = l & 3, n = l >> 2;
    const int col = 8 + pos*12 + n;
    const int pg = blockIdx.x*4;

    for (int i = tid; i < 48*64; i += 128) {
        int o = i >> 6, c = i & 63;
        float wv = (o<8) ? qw[o*64+c] : (o<16) ? kw[(o-8)*64+c] : vw[(o-16)*64+c];
        swt[c*52 + o] = wv;
    }
    if (tid < 48) sbs[tid] = (tid<8)? qb[tid] : (tid<16? kb[tid-8] : vb[tid-16]);
    for (int i = tid; i < 64*32; i += 128) {
        int c = i >> 5, ce = i & 31;
        int pp_ = ce & 3, nn = ce >> 2;
        xsm[c*COLW + (8 + pp_*12 + nn)] = src[(long)nn*CIN*PP + (long)c*PP + pg + pp_];
    }
    __syncthreads();

    u64 acc[6];
    {
        const u64* bp = (const u64*)sbs;
        #pragma unroll
        for (int t=0;t<6;t++) acc[t] = bp[wq*6 + t];
    }
    #pragma unroll 8
    for (int c=0;c<64;c++) {
        float xv = xsm[c*COLW + col];
        u64 x2 = pack2(xv,xv);
        const ulonglong2* wr = (const ulonglong2*)(swt + c*52 + wq*12);
        ulonglong2 w0 = wr[0], w1 = wr[1], w2 = wr[2];
        acc[0]=fma2(x2,w0.x,acc[0]); acc[1]=fma2(x2,w0.y,acc[1]);
        acc[2]=fma2(x2,w1.x,acc[2]); acc[3]=fma2(x2,w1.y,acc[3]);
        acc[4]=fma2(x2,w2.x,acc[4]); acc[5]=fma2(x2,w2.y,acc[5]);
    }
    float o12[12];
    #pragma unroll
    for (int t=0;t<6;t++) unpack2(acc[t], o12[2*t], o12[2*t+1]);
    const int p = pg + pos;
    #pragma unroll
    for (int t=0;t<12;t++) {
        int o = wq*12 + t;
        if (o < 8)       g_q[(n*8  + o     )*PP + p] = o12[t];
        else if (o < 16) g_k[(n*8  + (o-8) )*PP + p] = o12[t];
        else             g_v[(n*32 + (o-16))*PP + p] = fmaxf(o12[t], 0.f);
    }
}

// ---------------------------------------------------------------------------
// Visual attention, split-K ([t][j] smem layout — the known-good one).
// ---------------------------------------------------------------------------
__global__ __launch_bounds__(128) void vis_attn_split(void)
{
    __shared__ alignas(16) u64 ksu[4*128];    // [c2][j]
    __shared__ alignas(16) u64 vsu[16*128];   // [c2][j]
    const int tid = threadIdx.x;
    const int tile = blockIdx.x / NS, split = blockIdx.x % NS;
    const int n = tile / 6, tw = tile % 6;
    const int qp = tw*384 + tid;
    const float* qb_ = g_q + n*8*PP;
    const float* kb_ = g_k + n*8*PP;
    const float* vb_ = g_v + n*32*PP;

    u64 qr[3][4];
    #pragma unroll
    for (int i=0;i<3;i++)
        #pragma unroll
        for (int r=0;r<4;r++)
            qr[i][r] = pack2(qb_[(2*r)*PP + qp + i*128], qb_[(2*r+1)*PP + qp + i*128]);

    float l[3] = {0.f, 0.f, 0.f};
    u64 vacc[3][16];
    #pragma unroll
    for (int i=0;i<3;i++)
        #pragma unroll
        for (int t=0;t<16;t++) vacc[i][t] = 0ULL;

    const u64 z = 0ULL;
    for (int ch = split*2; ch < split*2 + 2; ch++) {
        __syncthreads();
        const int base = ch*128 + tid;
        #pragma unroll
        for (int r=0;r<4;r++)  ksu[r*128+tid] = pack2(kb_[(2*r)*PP+base], kb_[(2*r+1)*PP+base]);
        #pragma unroll
        for (int t=0;t<16;t++) vsu[t*128+tid] = pack2(vb_[(2*t)*PP+base], vb_[(2*t+1)*PP+base]);
        __syncthreads();
        #pragma unroll 2
        for (int j=0;j<128;j++) {
            u64 k0 = ksu[j], k1 = ksu[128+j], k2 = ksu[256+j], k3 = ksu[384+j];
            float pr[3];
            #pragma unroll
            for (int i=0;i<3;i++) {
                u64 d = add2(fma2(qr[i][0],k0,fma2(qr[i][1],k1,z)),
                             fma2(qr[i][2],k2,fma2(qr[i][3],k3,z)));
                float lo,hi; unpack2(d,lo,hi);
                pr[i] = __expf(lo + hi);
                l[i] += pr[i];
            }
            u64 p0 = pack2(pr[0],pr[0]), p1 = pack2(pr[1],pr[1]), p2 = pack2(pr[2],pr[2]);
            #pragma unroll
            for (int t=0;t<16;t++) {
                u64 vr = vsu[t*128+j];
                vacc[0][t] = fma2(p0, vr, vacc[0][t]);
                vacc[1][t] = fma2(p1, vr, vacc[1][t]);
                vacc[2][t] = fma2(p2, vr, vacc[2][t]);
            }
        }
    }
    #pragma unroll
    for (int i=0;i<3;i++) {
        int q = n*PP + qp + i*128;
        g_pl[split*QTOT + q] = l[i];
        #pragma unroll
        for (int t=0;t<16;t++) {
            float lo,hi; unpack2(vacc[i][t], lo, hi);
            g_pv[(split*32 + 2*t  )*QTOT + q] = lo;
            g_pv[(split*32 + 2*t+1)*QTOT + q] = hi;
        }
    }
}

// ---------------------------------------------------------------------------
// Combine split-K partials (unchanged from passing versions).
// ---------------------------------------------------------------------------
__global__ __launch_bounds__(128) void combine_kernel(
    const float* __restrict__ cw, const float* __restrict__ cb,
    float* __restrict__ out)
{
    __shared__ alignas(16) u64 cwt[32*16];
    __shared__ alignas(16) float cbs[32];
    const int tid = threadIdx.x;
    for (int i = tid; i < 32*16; i += 128) {
        int c = i/16, t = i%16;
        cwt[i] = pack2(cw[(2*t)*32+c], cw[(2*t+1)*32+c]);
    }
    if (tid < 32) cbs[tid] = cb[tid];
    __syncthreads();

    const int gid = blockIdx.x*128 + tid;
    const int n = gid/PP, p = gid%PP;

    float l = 0.f;
    #pragma unroll
    for (int sp=0; sp<NS; sp++) l += g_pl[sp*QTOT + gid];
    float va[32];
    #pragma unroll
    for (int c=0;c<32;c++) va[c] = 0.f;
    for (int sp=0; sp<NS; sp++) {
        #pragma unroll
        for (int c=0;c<32;c++) va[c] += g_pv[(sp*32+c)*QTOT + gid];
    }
    float inv = 1.f / l;
    #pragma unroll
    for (int c=0;c<32;c++) va[c] *= inv;

    u64 acc[16];
    #pragma unroll
    for (int t=0;t<16;t++) acc[t] = pack2(cbs[2*t], cbs[2*t+1]);
    #pragma unroll
    for (int c=0;c<32;c++) {
        u64 x2 = pack2(va[c], va[c]);
        const ulonglong2* w2 = (const ulonglong2*)(cwt + c*16);
        #pragma unroll
        for (int t=0;t<8;t++){ ulonglong2 w = w2[t];
            acc[2*t] = fma2(x2,w.x,acc[2*t]); acc[2*t+1] = fma2(x2,w.y,acc[2*t+1]); }
    }
    float buf[64];
    #pragma unroll
    for (int t=0;t<16;t++) unpack2(acc[t], buf[2*t], buf[2*t+1]);
    #pragma unroll
    for (int c=0;c<32;c++) buf[32+c] = g_v[(n*32+c)*PP+p];

    float* ob = out + (long)n*NSTRIDE + p;
    #pragma unroll
    for (int o=0;o<32;o++) ob[o*PP] = buf[o];
    #pragma unroll
    for (int c=0;c<32;c++) ob[(32+c)*PP] = buf[32+c];

    float4* xp = (float4*)(g_x + ((long)p*8 + n)*64);
    #pragma unroll
    for (int t=0;t<16;t++) xp[t] = make_float4(buf[4*t],buf[4*t+1],buf[4*t+2],buf[4*t+3]);
}

// ---------------------------------------------------------------------------
// MEGA temporal v5: round-7 structure (2 cells/thread, 64 cells/block) with
// the conflicted per-head weight transpose replaced by a linear float4 copy
// from the pre-transposed g_wt (conflict-free STS.128). cwt pitch = 32.
// ---------------------------------------------------------------------------
__global__ __launch_bounds__(128) void mega_temporal(
    const float* __restrict__ tq_b, const float* __restrict__ tk_b,
    const float* __restrict__ tv_b, const float* __restrict__ tc_b,
    float* __restrict__ out)
{
    __shared__ alignas(16) float swt[64*48];     // qkv weights [c][o] pitch 48
    __shared__ alignas(16) float cwt[32*32];     // conv weights [c][o] pitch 32
    __shared__ alignas(16) float sbs[48];
    __shared__ alignas(16) float cbs[32];
    __shared__ alignas(16) float xsm[64*68];     // head input [cell][c], pitch 68
    __shared__ alignas(16) float qkvsm[66*52];   // rows 0,1 = zero guards; row(cell)=2+cell

    const int tid  = threadIdx.x;
    const int wq   = tid >> 5, cp = tid & 31;
    const int posA = cp >> 3, n = cp & 7;
    const int cellA = cp, cellB = cp + 32;
    const int rowA = 2 + cellA, rowB = 2 + cellB;
    const int pg   = blockIdx.x*8;

    // zero qkvsm (guard rows 0,1 stay zero forever)
    for (int i = tid; i < 66*52; i += 128) qkvsm[i] = 0.f;

    // head-0 input: each thread loads its c-quarter for both cells
    {
        const float* gA = g_x + ((long)(pg+posA  )*8 + n)*64 + wq*16;
        const float* gB = g_x + ((long)(pg+posA+4)*8 + n)*64 + wq*16;
        #pragma unroll
        for (int k=0;k<4;k++) {
            *(float4*)(xsm + cellA*68 + wq*16 + 4*k) = *(const float4*)(gA + 4*k);
            *(float4*)(xsm + cellB*68 + wq*16 + 4*k) = *(const float4*)(gB + 4*k);
        }
    }

    for (int h=0; h<5; h++) {
        __syncthreads();   // barrier A: xsm writes done, prev weight reads done

        // ---- weights for head h: LINEAR float4 copy (conflict-free)
        {
            const float4* wt4 = (const float4*)(g_wt + h*4096);
            float4* s4 = (float4*)swt;
            float4* c4p = (float4*)cwt;
            #pragma unroll
            for (int k=0;k<6;k++) s4[tid + 128*k] = wt4[tid + 128*k];       // 768 float4
            #pragma unroll
            for (int k=0;k<2;k++) c4p[tid + 128*k] = wt4[768 + tid + 128*k]; // 256 float4
        }
        if (tid < 48) sbs[tid] = (tid<8)? tq_b[h*8+tid] : (tid<16? tk_b[h*8+tid-8] : tv_b[h*32+tid-16]);
        if (tid < 32) cbs[tid] = tc_b[h*32+tid];
        __syncthreads();   // barrier B: weights ready

        // ---- phase 1: qkv 64->48, outputs [12wq,12wq+12) for BOTH cells
        u64 accA[6], accB[6];
        {
            const u64* bp = (const u64*)sbs;
            #pragma unroll
            for (int t=0;t<6;t++) { accA[t] = bp[wq*6 + t]; accB[t] = accA[t]; }
        }
        #pragma unroll
        for (int c4=0; c4<64; c4+=4) {
            float4 xa = *(const float4*)(xsm + cellA*68 + c4);
            float4 xb = *(const float4*)(xsm + cellB*68 + c4);
            float xas[4] = {xa.x, xa.y, xa.z, xa.w};
            float xbs[4] = {xb.x, xb.y, xb.z, xb.w};
            #pragma unroll
            for (int j=0;j<4;j++) {
                u64 x2a = pack2(xas[j], xas[j]);
                u64 x2b = pack2(xbs[j], xbs[j]);
                const ulonglong2* wr = (const ulonglong2*)(swt + (c4+j)*48 + wq*12);
                ulonglong2 w0 = wr[0], w1 = wr[1], w2 = wr[2];
                accA[0]=fma2(x2a,w0.x,accA[0]); accA[1]=fma2(x2a,w0.y,accA[1]);
                accA[2]=fma2(x2a,w1.x,accA[2]); accA[3]=fma2(x2a,w1.y,accA[3]);
                accA[4]=fma2(x2a,w2.x,accA[4]); accA[5]=fma2(x2a,w2.y,accA[5]);
                accB[0]=fma2(x2b,w0.x,accB[0]); accB[1]=fma2(x2b,w0.y,accB[1]);
                accB[2]=fma2(x2b,w1.x,accB[2]); accB[3]=fma2(x2b,w1.y,accB[3]);
                accB[4]=fma2(x2b,w2.x,accB[4]); accB[5]=fma2(x2b,w2.y,accB[5]);
            }
        }
        {
            float oA[12], oB[12];
            #pragma unroll
            for (int t=0;t<6;t++) { unpack2(accA[t], oA[2*t], oA[2*t+1]);
                                    unpack2(accB[t], oB[2*t], oB[2*t+1]); }
            #pragma unroll
            for (int t=0;t<12;t++) if (12*wq + t >= 16) {
                oA[t] = fmaxf(oA[t], 0.f); oB[t] = fmaxf(oB[t], 0.f);
            }
            float* ra = qkvsm + rowA*52 + wq*12;
            float* rb = qkvsm + rowB*52 + wq*12;
            *(float4*)(ra  ) = make_float4(oA[0],oA[1],oA[2],oA[3]);
            *(float4*)(ra+4) = make_float4(oA[4],oA[5],oA[6],oA[7]);
            *(float4*)(ra+8) = make_float4(oA[8],oA[9],oA[10],oA[11]);
            *(float4*)(rb  ) = make_float4(oB[0],oB[1],oB[2],oB[3]);
            *(float4*)(rb+4) = make_float4(oB[4],oB[5],oB[6],oB[7]);
            *(float4*)(rb+8) = make_float4(oB[8],oB[9],oB[10],oB[11]);
        }
        __syncthreads();   // barrier C: qkv ready

        // ---- softmax (both cells, all threads redundantly)
        float a0A,a1A,a2A, a0B,a1B,a2B;
        {
            const float* rp = qkvsm + rowA*52;
            float4 q0=*(const float4*)(rp),     q1=*(const float4*)(rp+4);
            float4 k0a=*(const float4*)(rp+8),  k0b=*(const float4*)(rp+12);
            float4 k1a=*(const float4*)(rp+8-52),  k1b=*(const float4*)(rp+12-52);
            float4 k2a=*(const float4*)(rp+8-104), k2b=*(const float4*)(rp+12-104);
            float l2 = dot4(q0,k0a)+dot4(q1,k0b);
            float l1 = (n>=1) ? dot4(q0,k1a)+dot4(q1,k1b) : 0.f;
            float l0 = (n>=2) ? dot4(q0,k2a)+dot4(q1,k2b) : 0.f;
            float m  = fmaxf(l0, fmaxf(l1, l2));
            float e0=__expf(l0-m), e1=__expf(l1-m), e2=__expf(l2-m);
            float inv = 1.f/(e0+e1+e2);
            a2A = e2*inv;
            a1A = (n>=1) ? e1*inv : 0.f;
            a0A = (n>=2) ? e0*inv : 0.f;
        }
        {
            const float* rp = qkvsm + rowB*52;
            float4 q0=*(const float4*)(rp),     q1=*(const float4*)(rp+4);
            float4 k0a=*(const float4*)(rp+8),  k0b=*(const float4*)(rp+12);
            float4 k1a=*(const float4*)(rp+8-52),  k1b=*(const float4*)(rp+12-52);
            float4 k2a=*(const float4*)(rp+8-104), k2b=*(const float4*)(rp+12-104);
            float l2 = dot4(q0,k0a)+dot4(q1,k0b);
            float l1 = (n>=1) ? dot4(q0,k1a)+dot4(q1,k1b) : 0.f;
            float l0 = (n>=2) ? dot4(q0,k2a)+dot4(q1,k2b) : 0.f;
            float m  = fmaxf(l0, fmaxf(l1, l2));
            float e0=__expf(l0-m), e1=__expf(l1-m), e2=__expf(l2-m);
            float inv = 1.f/(e0+e1+e2);
            a2B = e2*inv;
            a1B = (n>=1) ? e1*inv : 0.f;
            a0B = (n>=2) ? e0*inv : 0.f;
        }

        // ---- fused attention-combine + out-conv, outputs [8wq,8wq+8), both cells
        u64 cA[4], cB[4];
        {
            const u64* bp = (const u64*)cbs;
            #pragma unroll
            for (int t=0;t<4;t++) { cA[t] = bp[wq*4 + t]; cB[t] = cA[t]; }
        }
        #pragma unroll
        for (int c4=0; c4<32; c4+=4) {
            const float* vra = qkvsm + rowA*52 + 16 + c4;
            const float* vrb = qkvsm + rowB*52 + 16 + c4;
            float4 v0a=*(const float4*)(vra), v1a=*(const float4*)(vra-52), v2a=*(const float4*)(vra-104);
            float4 v0b=*(const float4*)(vrb), v1b=*(const float4*)(vrb-52), v2b=*(const float4*)(vrb-104);
            float avA[4], avB[4];
            avA[0]=a2A*v0a.x+a1A*v1a.x+a0A*v2a.x; avA[1]=a2A*v0a.y+a1A*v1a.y+a0A*v2a.y;
            avA[2]=a2A*v0a.z+a1A*v1a.z+a0A*v2a.z; avA[3]=a2A*v0a.w+a1A*v1a.w+a0A*v2a.w;
            avB[0]=a2B*v0b.x+a1B*v1b.x+a0B*v2b.x; avB[1]=a2B*v0b.y+a1B*v1b.y+a0B*v2b.y;
            avB[2]=a2B*v0b.z+a1B*v1b.z+a0B*v2b.z; avB[3]=a2B*v0b.w+a1B*v1b.w+a0B*v2b.w;
            #pragma unroll
            for (int j=0;j<4;j++) {
                u64 x2a = pack2(avA[j], avA[j]);
                u64 x2b = pack2(avB[j], avB[j]);
                const ulonglong2* wr = (const ulonglong2*)(cwt + (c4+j)*32 + wq*8);
                ulonglong2 w0 = wr[0], w1 = wr[1];
                cA[0]=fma2(x2a,w0.x,cA[0]); cA[1]=fma2(x2a,w0.y,cA[1]);
                cA[2]=fma2(x2a,w1.x,cA[2]); cA[3]=fma2(x2a,w1.y,cA[3]);
                cB[0]=fma2(x2b,w0.x,cB[0]); cB[1]=fma2(x2b,w0.y,cB[1]);
                cB[2]=fma2(x2b,w1.x,cB[2]); cB[3]=fma2(x2b,w1.y,cB[3]);
            }
        }
        {
            float ocA[8], ocB[8];
            #pragma unroll
            for (int t=0;t<4;t++) { unpack2(cA[t], ocA[2*t], ocA[2*t+1]);
                                    unpack2(cB[t], ocB[2*t], ocB[2*t+1]); }
            float4 vaA = *(const float4*)(qkvsm + rowA*52 + 16 + wq*8);
            float4 vbA = *(const float4*)(qkvsm + rowA*52 + 16 + wq*8 + 4);
            float4 vaB = *(const float4*)(qkvsm + rowB*52 + 16 + wq*8);
            float4 vbB = *(const float4*)(qkvsm + rowB*52 + 16 + wq*8 + 4);
            float vqA[8] = {vaA.x,vaA.y,vaA.z,vaA.w, vbA.x,vbA.y,vbA.z,vbA.w};
            float vqB[8] = {vaB.x,vaB.y,vaB.z,vaB.w, vbB.x,vbB.y,vbB.z,vbB.w};

            float* obA = out + (long)n*NSTRIDE + (long)(h+1)*SLICE + pg + posA;
            float* obB = obA + 4;
            #pragma unroll
            for (int j=0;j<8;j++) {
                obA[(8*wq+j)*PP]    = ocA[j];
                obA[(32+8*wq+j)*PP] = vqA[j];
                obB[(8*wq+j)*PP]    = ocB[j];
                obB[(32+8*wq+j)*PP] = vqB[j];
            }
            // next head input (barrier A protects readers)
            float* xrA = xsm + cellA*68;
            float* xrB = xsm + cellB*68;
            *(float4*)(xrA + 8*wq    ) = make_float4(ocA[0],ocA[1],ocA[2],ocA[3]);
            *(float4*)(xrA + 8*wq + 4) = make_float4(ocA[4],ocA[5],ocA[6],ocA[7]);
            *(float4*)(xrA + 32 + 8*wq    ) = vaA;
            *(float4*)(xrA + 32 + 8*wq + 4) = vbA;
            *(float4*)(xrB + 8*wq    ) = make_float4(ocB[0],ocB[1],ocB[2],ocB[3]);
            *(float4*)(xrB + 8*wq + 4) = make_float4(ocB[4],ocB[5],ocB[6],ocB[7]);
            *(float4*)(xrB + 32 + 8*wq    ) = vaB;
            *(float4*)(xrB + 32 + 8*wq + 4) = vbB;
        }
    }
}

// ---------------------------------------------------------------------------
extern "C" void kernel_launch(void* const* d_in, const int* in_sizes, int n_in,
                              void* d_out, int out_size)
{
    const float* x    = (const float*)d_in[0];
    const float* vq_w = (const float*)d_in[1];
    const float* vq_b = (const float*)d_in[2];
    const float* vk_w = (const float*)d_in[3];
    const float* vk_b = (const float*)d_in[4];
    const float* vv_w = (const float*)d_in[5];
    const float* vv_b = (const float*)d_in[6];
    const float* vc_w = (const float*)d_in[7];
    const float* vc_b = (const float*)d_in[8];
    const float* tq_w = (const float*)d_in[9];
    const float* tq_b = (const float*)d_in[10];
    const float* tk_w = (const float*)d_in[11];
    const float* tk_b = (const float*)d_in[12];
    const float* tv_w = (const float*)d_in[13];
    const float* tv_b = (const float*)d_in[14];
    const float* tc_w = (const float*)d_in[15];
    const float* tc_b = (const float*)d_in[16];
    float* out = (float*)d_out;

    transpose_w<<<80,256>>>(tq_w, tk_w, tv_w, tc_w);   // 5*4096 elements
    qkv0_kernel<<<576,128>>>(x, vq_w, vq_b, vk_w, vk_b, vv_w, vv_b);
    vis_attn_split<<<48*NS,128>>>();
    combine_kernel<<<144,128>>>(vc_w, vc_b, out);
    mega_temporal<<<288,128>>>(tq_b, tk_b, tv_b, tc_b, out);
}

// round 11
// speedup vs baseline: 1.4475x; 1.0120x over previous
#include <cuda_runtime.h>

#define NB 8
#define PP 2304
#define QTOT (NB*PP)       // 18432
#define CIN 64
#define OUTC 384
#define NSTRIDE (OUTC*PP)
#define SLICE (64*PP)
#define NS 9               // split-K factor for visual attention
#define COLW 56            // (qkv0 only) smem row width

// Scratch (allocation-free rule: __device__ globals)
__device__ float g_q[NB*8*PP];
__device__ float g_k[NB*8*PP];
__device__ float g_v[NB*32*PP];
__device__ float g_pl[NS*QTOT];
__device__ float g_pv[NS*32*QTOT];
__device__ float g_x[QTOT*64];     // [p][n][c] mega-kernel input
__device__ float g_wt[5*4096];     // per head: [64][48] qkv-T (3072) + [32][32] conv-T (1024)

typedef unsigned long long u64;

__device__ __forceinline__ u64 fma2(u64 a,u64 b,u64 c){u64 d;asm("fma.rn.f32x2 %0,%1,%2,%3;":"=l"(d):"l"(a),"l"(b),"l"(c));return d;}
__device__ __forceinline__ u64 add2(u64 a,u64 b){u64 d;asm("add.rn.f32x2 %0,%1,%2;":"=l"(d):"l"(a),"l"(b));return d;}
__device__ __forceinline__ u64 pack2(float lo,float hi){u64 d;asm("mov.b64 %0,{%1,%2};":"=l"(d):"f"(lo),"f"(hi));return d;}
__device__ __forceinline__ void unpack2(u64 v,float&lo,float&hi){asm("mov.b64 {%0,%1},%2;":"=f"(lo),"=f"(hi):"l"(v));}

__device__ __forceinline__ float dot4(float4 a, float4 b){
    return a.x*b.x + a.y*b.y + a.z*b.z + a.w*b.w;
}

// ---------------------------------------------------------------------------
// One-shot weight transpose: [o][c] (gmem) -> [c][o] flat per head in g_wt.
// ---------------------------------------------------------------------------
__global__ __launch_bounds__(256) void transpose_w(
    const float* __restrict__ tq_w, const float* __restrict__ tk_w,
    const float* __restrict__ tv_w, const float* __restrict__ tc_w)
{
    int i = blockIdx.x*256 + threadIdx.x;
    if (i >= 5*4096) return;
    int h = i >> 12, r = i & 4095;
    float v;
    if (r < 3072) {
        int c = r / 48, o = r % 48;
        v = (o<8)  ? tq_w[h*512  + o*64 + c]
          : (o<16) ? tk_w[h*512  + (o-8)*64 + c]
                   : tv_w[h*2048 + (o-16)*64 + c];
    } else {
        int rr = r - 3072;
        int c = rr >> 5, o = rr & 31;
        v = tc_w[h*1024 + o*32 + c];
    }
    g_wt[i] = v;
}

// ---------------------------------------------------------------------------
// Stage-0 QKV, 4-way split (unchanged from passing versions).
// ---------------------------------------------------------------------------
__global__ __launch_bounds__(128) void qkv0_kernel(
    const float* __restrict__ src,
    const float* __restrict__ qw, const float* __restrict__ qb,
    const float* __restrict__ kw, const float* __restrict__ kb,
    const float* __restrict__ vw, const float* __restrict__ vb)
{
    __shared__ alignas(16) float swt[64*52];
    __shared__ alignas(16) float sbs[48];
    __shared__ alignas(16) float xsm[64*COLW];

    const int tid = threadIdx.x;
    const int wq = tid >> 5, l = tid & 31;
    const int pos = l & 3, n = l >> 2;
    const int col = 8 + pos*12 + n;
    const int pg = blockIdx.x*4;

    for (int i = tid; i < 48*64; i += 128) {
        int o = i >> 6, c = i & 63;
        float wv = (o<8) ? qw[o*64+c] : (o<16) ? kw[(o-8)*64+c] : vw[(o-16)*64+c];
        swt[c*52 + o] = wv;
    }
    if (tid < 48) sbs[tid] = (tid<8)? qb[tid] : (tid<16? kb[tid-8] : vb[tid-16]);
    for (int i = tid; i < 64*32; i += 128) {
        int c = i >> 5, ce = i & 31;
        int pp_ = ce & 3, nn = ce >> 2;
        xsm[c*COLW + (8 + pp_*12 + nn)] = src[(long)nn*CIN*PP + (long)c*PP + pg + pp_];
    }
    __syncthreads();

    u64 acc[6];
    {
        const u64* bp = (const u64*)sbs;
        #pragma unroll
        for (int t=0;t<6;t++) acc[t] = bp[wq*6 + t];
    }
    #pragma unroll 8
    for (int c=0;c<64;c++) {
        float xv = xsm[c*COLW + col];
        u64 x2 = pack2(xv,xv);
        const ulonglong2* wr = (const ulonglong2*)(swt + c*52 + wq*12);
        ulonglong2 w0 = wr[0], w1 = wr[1], w2 = wr[2];
        acc[0]=fma2(x2,w0.x,acc[0]); acc[1]=fma2(x2,w0.y,acc[1]);
        acc[2]=fma2(x2,w1.x,acc[2]); acc[3]=fma2(x2,w1.y,acc[3]);
        acc[4]=fma2(x2,w2.x,acc[4]); acc[5]=fma2(x2,w2.y,acc[5]);
    }
    float o12[12];
    #pragma unroll
    for (int t=0;t<6;t++) unpack2(acc[t], o12[2*t], o12[2*t+1]);
    const int p = pg + pos;
    #pragma unroll
    for (int t=0;t<12;t++) {
        int o = wq*12 + t;
        if (o < 8)       g_q[(n*8  + o     )*PP + p] = o12[t];
        else if (o < 16) g_k[(n*8  + (o-8) )*PP + p] = o12[t];
        else             g_v[(n*32 + (o-16))*PP + p] = fmaxf(o12[t], 0.f);
    }
}

// ---------------------------------------------------------------------------
// Visual attention, split-K ([t][j] smem layout — the known-good one).
// ---------------------------------------------------------------------------
__global__ __launch_bounds__(128) void vis_attn_split(void)
{
    __shared__ alignas(16) u64 ksu[4*128];    // [c2][j]
    __shared__ alignas(16) u64 vsu[16*128];   // [c2][j]
    const int tid = threadIdx.x;
    const int tile = blockIdx.x / NS, split = blockIdx.x % NS;
    const int n = tile / 6, tw = tile % 6;
    const int qp = tw*384 + tid;
    const float* qb_ = g_q + n*8*PP;
    const float* kb_ = g_k + n*8*PP;
    const float* vb_ = g_v + n*32*PP;

    u64 qr[3][4];
    #pragma unroll
    for (int i=0;i<3;i++)
        #pragma unroll
        for (int r=0;r<4;r++)
            qr[i][r] = pack2(qb_[(2*r)*PP + qp + i*128], qb_[(2*r+1)*PP + qp + i*128]);

    float l[3] = {0.f, 0.f, 0.f};
    u64 vacc[3][16];
    #pragma unroll
    for (int i=0;i<3;i++)
        #pragma unroll
        for (int t=0;t<16;t++) vacc[i][t] = 0ULL;

    const u64 z = 0ULL;
    for (int ch = split*2; ch < split*2 + 2; ch++) {
        __syncthreads();
        const int base = ch*128 + tid;
        #pragma unroll
        for (int r=0;r<4;r++)  ksu[r*128+tid] = pack2(kb_[(2*r)*PP+base], kb_[(2*r+1)*PP+base]);
        #pragma unroll
        for (int t=0;t<16;t++) vsu[t*128+tid] = pack2(vb_[(2*t)*PP+base], vb_[(2*t+1)*PP+base]);
        __syncthreads();
        #pragma unroll 2
        for (int j=0;j<128;j++) {
            u64 k0 = ksu[j], k1 = ksu[128+j], k2 = ksu[256+j], k3 = ksu[384+j];
            float pr[3];
            #pragma unroll
            for (int i=0;i<3;i++) {
                u64 d = add2(fma2(qr[i][0],k0,fma2(qr[i][1],k1,z)),
                             fma2(qr[i][2],k2,fma2(qr[i][3],k3,z)));
                float lo,hi; unpack2(d,lo,hi);
                pr[i] = __expf(lo + hi);
                l[i] += pr[i];
            }
            u64 p0 = pack2(pr[0],pr[0]), p1 = pack2(pr[1],pr[1]), p2 = pack2(pr[2],pr[2]);
            #pragma unroll
            for (int t=0;t<16;t++) {
                u64 vr = vsu[t*128+j];
                vacc[0][t] = fma2(p0, vr, vacc[0][t]);
                vacc[1][t] = fma2(p1, vr, vacc[1][t]);
                vacc[2][t] = fma2(p2, vr, vacc[2][t]);
            }
        }
    }
    #pragma unroll
    for (int i=0;i<3;i++) {
        int q = n*PP + qp + i*128;
        g_pl[split*QTOT + q] = l[i];
        #pragma unroll
        for (int t=0;t<16;t++) {
            float lo,hi; unpack2(vacc[i][t], lo, hi);
            g_pv[(split*32 + 2*t  )*QTOT + q] = lo;
            g_pv[(split*32 + 2*t+1)*QTOT + q] = hi;
        }
    }
}

// ---------------------------------------------------------------------------
// Combine v2: 4 threads per position (warp wq owns channels [8wq,8wq+8)).
// Grid 576 x 128 = 4x the warps of v1; per-thread partial loads drop 288->72.
// av staged in smem pitch 33 (conflict-free scalar LDS/STS).
// ---------------------------------------------------------------------------
__global__ __launch_bounds__(128) void combine_kernel(
    const float* __restrict__ cw, const float* __restrict__ cb,
    float* __restrict__ out)
{
    __shared__ alignas(16) u64 cwt[32*16];    // [c][o2]
    __shared__ alignas(16) float cbs[32];
    __shared__ alignas(16) float avs[32*33];  // [cell][c], pitch 33
    const int tid = threadIdx.x;
    const int wq = tid >> 5, cell = tid & 31;

    for (int i = tid; i < 32*16; i += 128) {
        int c = i/16, t = i%16;
        cwt[i] = pack2(cw[(2*t)*32+c], cw[(2*t+1)*32+c]);
    }
    if (tid < 32) cbs[tid] = cb[tid];

    const int gid = blockIdx.x*32 + cell;
    const int n = gid/PP, p = gid%PP;

    // reduce l over splits (redundant across the 4 wq threads of a cell)
    float l = 0.f;
    #pragma unroll
    for (int sp=0; sp<NS; sp++) l += g_pl[sp*QTOT + gid];

    // reduce this thread's 8 channels over splits (72 coalesced loads, high MLP)
    float va[8];
    #pragma unroll
    for (int j=0;j<8;j++) va[j] = 0.f;
    #pragma unroll
    for (int sp=0; sp<NS; sp++) {
        #pragma unroll
        for (int j=0;j<8;j++)
            va[j] += g_pv[(sp*32 + wq*8 + j)*QTOT + gid];
    }
    float inv = 1.f / l;
    #pragma unroll
    for (int j=0;j<8;j++) avs[cell*33 + wq*8 + j] = va[j] * inv;
    __syncthreads();

    // conv 32->32: warp wq computes outputs [8wq,8wq+8) for its cell
    u64 acc[4];
    {
        const u64* bp = (const u64*)cbs;
        #pragma unroll
        for (int t=0;t<4;t++) acc[t] = bp[wq*4 + t];
    }
    #pragma unroll 8
    for (int c=0;c<32;c++) {
        float av = avs[cell*33 + c];
        u64 x2 = pack2(av, av);
        const ulonglong2* wr = (const ulonglong2*)(cwt + c*16 + wq*4);
        ulonglong2 w0 = wr[0], w1 = wr[1];
        acc[0]=fma2(x2,w0.x,acc[0]); acc[1]=fma2(x2,w0.y,acc[1]);
        acc[2]=fma2(x2,w1.x,acc[2]); acc[3]=fma2(x2,w1.y,acc[3]);
    }
    float oc[8];
    #pragma unroll
    for (int t=0;t<4;t++) unpack2(acc[t], oc[2*t], oc[2*t+1]);

    // own 8 channels of v (coalesced LDG)
    float vv[8];
    #pragma unroll
    for (int j=0;j<8;j++) vv[j] = g_v[(n*32 + wq*8 + j)*PP + p];

    float* ob = out + (long)n*NSTRIDE + p;   // slice 0
    #pragma unroll
    for (int j=0;j<8;j++) {
        ob[(wq*8+j)*PP]      = oc[j];
        ob[(32+wq*8+j)*PP]   = vv[j];
    }

    float* xp = g_x + ((long)p*8 + n)*64;
    *(float4*)(xp + wq*8    ) = make_float4(oc[0],oc[1],oc[2],oc[3]);
    *(float4*)(xp + wq*8 + 4) = make_float4(oc[4],oc[5],oc[6],oc[7]);
    *(float4*)(xp + 32 + wq*8    ) = make_float4(vv[0],vv[1],vv[2],vv[3]);
    *(float4*)(xp + 32 + wq*8 + 4) = make_float4(vv[4],vv[5],vv[6],vv[7]);
}

// ---------------------------------------------------------------------------
// MEGA temporal v5 (unchanged from the 146 us version).
// ---------------------------------------------------------------------------
__global__ __launch_bounds__(128) void mega_temporal(
    const float* __restrict__ tq_b, const float* __restrict__ tk_b,
    const float* __restrict__ tv_b, const float* __restrict__ tc_b,
    float* __restrict__ out)
{
    __shared__ alignas(16) float swt[64*48];     // qkv weights [c][o] pitch 48
    __shared__ alignas(16) float cwt[32*32];     // conv weights [c][o] pitch 32
    __shared__ alignas(16) float sbs[48];
    __shared__ alignas(16) float cbs[32];
    __shared__ alignas(16) float xsm[64*68];     // head input [cell][c], pitch 68
    __shared__ alignas(16) float qkvsm[66*52];   // rows 0,1 = zero guards; row(cell)=2+cell

    const int tid  = threadIdx.x;
    const int wq   = tid >> 5, cp = tid & 31;
    const int posA = cp >> 3, n = cp & 7;
    const int cellA = cp, cellB = cp + 32;
    const int rowA = 2 + cellA, rowB = 2 + cellB;
    const int pg   = blockIdx.x*8;

    for (int i = tid; i < 66*52; i += 128) qkvsm[i] = 0.f;

    {
        const float* gA = g_x + ((long)(pg+posA  )*8 + n)*64 + wq*16;
        const float* gB = g_x + ((long)(pg+posA+4)*8 + n)*64 + wq*16;
        #pragma unroll
        for (int k=0;k<4;k++) {
            *(float4*)(xsm + cellA*68 + wq*16 + 4*k) = *(const float4*)(gA + 4*k);
            *(float4*)(xsm + cellB*68 + wq*16 + 4*k) = *(const float4*)(gB + 4*k);
        }
    }

    for (int h=0; h<5; h++) {
        __syncthreads();   // barrier A

        {
            const float4* wt4 = (const float4*)(g_wt + h*4096);
            float4* s4 = (float4*)swt;
            float4* c4p = (float4*)cwt;
            #pragma unroll
            for (int k=0;k<6;k++) s4[tid + 128*k] = wt4[tid + 128*k];
            #pragma unroll
            for (int k=0;k<2;k++) c4p[tid + 128*k] = wt4[768 + tid + 128*k];
        }
        if (tid < 48) sbs[tid] = (tid<8)? tq_b[h*8+tid] : (tid<16? tk_b[h*8+tid-8] : tv_b[h*32+tid-16]);
        if (tid < 32) cbs[tid] = tc_b[h*32+tid];
        __syncthreads();   // barrier B

        u64 accA[6], accB[6];
        {
            const u64* bp = (const u64*)sbs;
            #pragma unroll
            for (int t=0;t<6;t++) { accA[t] = bp[wq*6 + t]; accB[t] = accA[t]; }
        }
        #pragma unroll
        for (int c4=0; c4<64; c4+=4) {
            float4 xa = *(const float4*)(xsm + cellA*68 + c4);
            float4 xb = *(const float4*)(xsm + cellB*68 + c4);
            float xas[4] = {xa.x, xa.y, xa.z, xa.w};
            float xbs[4] = {xb.x, xb.y, xb.z, xb.w};
            #pragma unroll
            for (int j=0;j<4;j++) {
                u64 x2a = pack2(xas[j], xas[j]);
                u64 x2b = pack2(xbs[j], xbs[j]);
                const ulonglong2* wr = (const ulonglong2*)(swt + (c4+j)*48 + wq*12);
                ulonglong2 w0 = wr[0], w1 = wr[1], w2 = wr[2];
                accA[0]=fma2(x2a,w0.x,accA[0]); accA[1]=fma2(x2a,w0.y,accA[1]);
                accA[2]=fma2(x2a,w1.x,accA[2]); accA[3]=fma2(x2a,w1.y,accA[3]);
                accA[4]=fma2(x2a,w2.x,accA[4]); accA[5]=fma2(x2a,w2.y,accA[5]);
                accB[0]=fma2(x2b,w0.x,accB[0]); accB[1]=fma2(x2b,w0.y,accB[1]);
                accB[2]=fma2(x2b,w1.x,accB[2]); accB[3]=fma2(x2b,w1.y,accB[3]);
                accB[4]=fma2(x2b,w2.x,accB[4]); accB[5]=fma2(x2b,w2.y,accB[5]);
            }
        }
        {
            float oA[12], oB[12];
            #pragma unroll
            for (int t=0;t<6;t++) { unpack2(accA[t], oA[2*t], oA[2*t+1]);
                                    unpack2(accB[t], oB[2*t], oB[2*t+1]); }
            #pragma unroll
            for (int t=0;t<12;t++) if (12*wq + t >= 16) {
                oA[t] = fmaxf(oA[t], 0.f); oB[t] = fmaxf(oB[t], 0.f);
            }
            float* ra = qkvsm + rowA*52 + wq*12;
            float* rb = qkvsm + rowB*52 + wq*12;
            *(float4*)(ra  ) = make_float4(oA[0],oA[1],oA[2],oA[3]);
            *(float4*)(ra+4) = make_float4(oA[4],oA[5],oA[6],oA[7]);
            *(float4*)(ra+8) = make_float4(oA[8],oA[9],oA[10],oA[11]);
            *(float4*)(rb  ) = make_float4(oB[0],oB[1],oB[2],oB[3]);
            *(float4*)(rb+4) = make_float4(oB[4],oB[5],oB[6],oB[7]);
            *(float4*)(rb+8) = make_float4(oB[8],oB[9],oB[10],oB[11]);
        }
        __syncthreads();   // barrier C

        float a0A,a1A,a2A, a0B,a1B,a2B;
        {
            const float* rp = qkvsm + rowA*52;
            float4 q0=*(const float4*)(rp),     q1=*(const float4*)(rp+4);
            float4 k0a=*(const float4*)(rp+8),  k0b=*(const float4*)(rp+12);
            float4 k1a=*(const float4*)(rp+8-52),  k1b=*(const float4*)(rp+12-52);
            float4 k2a=*(const float4*)(rp+8-104), k2b=*(const float4*)(rp+12-104);
            float l2 = dot4(q0,k0a)+dot4(q1,k0b);
            float l1 = (n>=1) ? dot4(q0,k1a)+dot4(q1,k1b) : 0.f;
            float l0 = (n>=2) ? dot4(q0,k2a)+dot4(q1,k2b) : 0.f;
            float m  = fmaxf(l0, fmaxf(l1, l2));
            float e0=__expf(l0-m), e1=__expf(l1-m), e2=__expf(l2-m);
            float inv = 1.f/(e0+e1+e2);
            a2A = e2*inv;
            a1A = (n>=1) ? e1*inv : 0.f;
            a0A = (n>=2) ? e0*inv : 0.f;
        }
        {
            const float* rp = qkvsm + rowB*52;
            float4 q0=*(const float4*)(rp),     q1=*(const float4*)(rp+4);
            float4 k0a=*(const float4*)(rp+8),  k0b=*(const float4*)(rp+12);
            float4 k1a=*(const float4*)(rp+8-52),  k1b=*(const float4*)(rp+12-52);
            float4 k2a=*(const float4*)(rp+8-104), k2b=*(const float4*)(rp+12-104);
            float l2 = dot4(q0,k0a)+dot4(q1,k0b);
            float l1 = (n>=1) ? dot4(q0,k1a)+dot4(q1,k1b) : 0.f;
            float l0 = (n>=2) ? dot4(q0,k2a)+dot4(q1,k2b) : 0.f;
            float m  = fmaxf(l0, fmaxf(l1, l2));
            float e0=__expf(l0-m), e1=__expf(l1-m), e2=__expf(l2-m);
            float inv = 1.f/(e0+e1+e2);
            a2B = e2*inv;
            a1B = (n>=1) ? e1*inv : 0.f;
            a0B = (n>=2) ? e0*inv : 0.f;
        }

        u64 cA[4], cB[4];
        {
            const u64* bp = (const u64*)cbs;
            #pragma unroll
            for (int t=0;t<4;t++) { cA[t] = bp[wq*4 + t]; cB[t] = cA[t]; }
        }
        #pragma unroll
        for (int c4=0; c4<32; c4+=4) {
            const float* vra = qkvsm + rowA*52 + 16 + c4;
            const float* vrb = qkvsm + rowB*52 + 16 + c4;
            float4 v0a=*(const float4*)(vra), v1a=*(const float4*)(vra-52), v2a=*(const float4*)(vra-104);
            float4 v0b=*(const float4*)(vrb), v1b=*(const float4*)(vrb-52), v2b=*(const float4*)(vrb-104);
            float avA[4], avB[4];
            avA[0]=a2A*v0a.x+a1A*v1a.x+a0A*v2a.x; avA[1]=a2A*v0a.y+a1A*v1a.y+a0A*v2a.y;
            avA[2]=a2A*v0a.z+a1A*v1a.z+a0A*v2a.z; avA[3]=a2A*v0a.w+a1A*v1a.w+a0A*v2a.w;
            avB[0]=a2B*v0b.x+a1B*v1b.x+a0B*v2b.x; avB[1]=a2B*v0b.y+a1B*v1b.y+a0B*v2b.y;
            avB[2]=a2B*v0b.z+a1B*v1b.z+a0B*v2b.z; avB[3]=a2B*v0b.w+a1B*v1b.w+a0B*v2b.w;
            #pragma unroll
            for (int j=0;j<4;j++) {
                u64 x2a = pack2(avA[j], avA[j]);
                u64 x2b = pack2(avB[j], avB[j]);
                const ulonglong2* wr = (const ulonglong2*)(cwt + (c4+j)*32 + wq*8);
                ulonglong2 w0 = wr[0], w1 = wr[1];
                cA[0]=fma2(x2a,w0.x,cA[0]); cA[1]=fma2(x2a,w0.y,cA[1]);
                cA[2]=fma2(x2a,w1.x,cA[2]); cA[3]=fma2(x2a,w1.y,cA[3]);
                cB[0]=fma2(x2b,w0.x,cB[0]); cB[1]=fma2(x2b,w0.y,cB[1]);
                cB[2]=fma2(x2b,w1.x,cB[2]); cB[3]=fma2(x2b,w1.y,cB[3]);
            }
        }
        {
            float ocA[8], ocB[8];
            #pragma unroll
            for (int t=0;t<4;t++) { unpack2(cA[t], ocA[2*t], ocA[2*t+1]);
                                    unpack2(cB[t], ocB[2*t], ocB[2*t+1]); }
            float4 vaA = *(const float4*)(qkvsm + rowA*52 + 16 + wq*8);
            float4 vbA = *(const float4*)(qkvsm + rowA*52 + 16 + wq*8 + 4);
            float4 vaB = *(const float4*)(qkvsm + rowB*52 + 16 + wq*8);
            float4 vbB = *(const float4*)(qkvsm + rowB*52 + 16 + wq*8 + 4);
            float vqA[8] = {vaA.x,vaA.y,vaA.z,vaA.w, vbA.x,vbA.y,vbA.z,vbA.w};
            float vqB[8] = {vaB.x,vaB.y,vaB.z,vaB.w, vbB.x,vbB.y,vbB.z,vbB.w};

            float* obA = out + (long)n*NSTRIDE + (long)(h+1)*SLICE + pg + posA;
            float* obB = obA + 4;
            #pragma unroll
            for (int j=0;j<8;j++) {
                obA[(8*wq+j)*PP]    = ocA[j];
                obA[(32+8*wq+j)*PP] = vqA[j];
                obB[(8*wq+j)*PP]    = ocB[j];
                obB[(32+8*wq+j)*PP] = vqB[j];
            }
            float* xrA = xsm + cellA*68;
            float* xrB = xsm + cellB*68;
            *(float4*)(xrA + 8*wq    ) = make_float4(ocA[0],ocA[1],ocA[2],ocA[3]);
            *(float4*)(xrA + 8*wq + 4) = make_float4(ocA[4],ocA[5],ocA[6],ocA[7]);
            *(float4*)(xrA + 32 + 8*wq    ) = vaA;
            *(float4*)(xrA + 32 + 8*wq + 4) = vbA;
            *(float4*)(xrB + 8*wq    ) = make_float4(ocB[0],ocB[1],ocB[2],ocB[3]);
            *(float4*)(xrB + 8*wq + 4) = make_float4(ocB[4],ocB[5],ocB[6],ocB[7]);
            *(float4*)(xrB + 32 + 8*wq    ) = vaB;
            *(float4*)(xrB + 32 + 8*wq + 4) = vbB;
        }
    }
}

// ---------------------------------------------------------------------------
extern "C" void kernel_launch(void* const* d_in, const int* in_sizes, int n_in,
                              void* d_out, int out_size)
{
    const float* x    = (const float*)d_in[0];
    const float* vq_w = (const float*)d_in[1];
    const float* vq_b = (const float*)d_in[2];
    const float* vk_w = (const float*)d_in[3];
    const float* vk_b = (const float*)d_in[4];
    const float* vv_w = (const float*)d_in[5];
    const float* vv_b = (const float*)d_in[6];
    const float* vc_w = (const float*)d_in[7];
    const float* vc_b = (const float*)d_in[8];
    const float* tq_w = (const float*)d_in[9];
    const float* tq_b = (const float*)d_in[10];
    const float* tk_w = (const float*)d_in[11];
    const float* tk_b = (const float*)d_in[12];
    const float* tv_w = (const float*)d_in[13];
    const float* tv_b = (const float*)d_in[14];
    const float* tc_w = (const float*)d_in[15];
    const float* tc_b = (const float*)d_in[16];
    float* out = (float*)d_out;

    transpose_w<<<80,256>>>(tq_w, tk_w, tv_w, tc_w);
    qkv0_kernel<<<576,128>>>(x, vq_w, vq_b, vk_w, vk_b, vv_w, vv_b);
    vis_attn_split<<<48*NS,128>>>();
    combine_kernel<<<576,128>>>(vc_w, vc_b, out);
    mega_temporal<<<288,128>>>(tq_b, tk_b, tv_b, tc_b, out);
}